// round 16
// baseline (speedup 1.0000x reference)
#include <cuda_runtime.h>
#include <cuda_bf16.h>

// Integrate-and-fire spiking neuron, 3 phases, per-pixel independent.
// T1 = T2 = 8, L = 8, EPS = -8e-5, thre = thresh[0]/8.
//
// x layout:   x[t*S + p]   for t in [0,8), p in [0, S) with S = B*C*H*W
// out layout: out[t*S + p]
//
// R15: the persistent-wave test, de-confounded. R14's grid-stride loop let
// ptxas go to 40 regs (occ 61%) which masked the experiment — the empirical
// law across 7 builds is: 32 regs/80% occ -> ~37.6us, 40 regs/60% occ ->
// ~39.4us. Force the 32-reg budget with __launch_bounds__(128, 16)
// (64K regs / 2048 thr = 32/thread) and keep one resident wave
// (152 SMs x 16 blocks = 2432 CTAs). Running pointers minimize loop-carried
// state so the body fits the budget.

#define IF_T1 8
#define IF_T2 8
#define IF_RELAX 7            // T3 - 1 = max(T1,T2) - 1
#define IF_EPS (-8e-05f)

#define IF_BLOCKS 2432        // 152 SMs * 16 resident blocks
#define IF_THREADS 128

__global__ __launch_bounds__(IF_THREADS, 16)   // force <=32 regs/thread
void IF_88957362634870_kernel(const float4* __restrict__ x,
                              const float* __restrict__ thresh,
                              float4* __restrict__ out,
                              int S4) {
    // thresh/L with L=8: *0.125f is exact (power of two), matches JAX fp32.
    const float thre = __ldg(thresh) * 0.125f;

    const int stride = IF_BLOCKS * IF_THREADS;
    int i = blockIdx.x * IF_THREADS + threadIdx.x;

    const float4* px   = x + i;     // running pointers: only loop-carried
    float4*       pout = out + i;   // state is (px, pout, i)

    for (; i < S4; i += stride, px += stride, pout += stride) {
        float mem[4], sc[4];
#pragma unroll
        for (int c = 0; c < 4; c++) {
            mem[c] = 0.5f * thre;
            sc[c]  = 0.0f;
        }

        // ---- Phase 1: integrate-and-fire over T1 frames ----
        // Two batches of 4 front-batched LDG.128s (MLP=4) fit 32 regs.
#pragma unroll
        for (int half = 0; half < 2; half++) {
            float4 xs[4];
#pragma unroll
            for (int t = 0; t < 4; t++) {
                xs[t] = __ldcs(px + (half * 4 + t) * S4);
            }
#pragma unroll
            for (int t = 0; t < 4; t++) {
                float xv[4] = {xs[t].x, xs[t].y, xs[t].z, xs[t].w};
#pragma unroll
                for (int c = 0; c < 4; c++) {
                    mem[c] = mem[c] + xv[c];
                    float spike = ((mem[c] - thre) >= IF_EPS) ? thre : 0.0f;
                    mem[c] = mem[c] - spike;
                    sc[c]  = sc[c] + spike;
                }
            }
        }

        // ---- Phase 2: T3-1 relaxation steps with reverse spikes ----
#pragma unroll
        for (int s = 0; s < IF_RELAX; s++) {
#pragma unroll
            for (int c = 0; c < 4; c++) {
                float spike = ((mem[c] - thre) >= IF_EPS) ? thre : 0.0f;
                float rev   = ((-mem[c]) > 0.0f) ? thre : 0.0f;
                mem[c] = (mem[c] - spike) + rev;   // same assoc order as JAX
                sc[c]  = (sc[c] + spike) - rev;
            }
        }

        // ---- Phase 3: re-emit spike count as T2 output spikes ----
        // Output is write-once, never re-read: evict-first streaming stores.
#pragma unroll
        for (int c = 0; c < 4; c++) mem[c] = sc[c];

#pragma unroll
        for (int t = 0; t < IF_T2; t++) {
            float sp[4];
#pragma unroll
            for (int c = 0; c < 4; c++) {
                sp[c]  = ((mem[c] - thre) >= IF_EPS) ? thre : 0.0f;
                mem[c] = mem[c] - sp[c];
            }
            float4 o;
            o.x = sp[0]; o.y = sp[1]; o.z = sp[2]; o.w = sp[3];
            __stcs(pout + t * S4, o);
        }
    }
}

extern "C" void kernel_launch(void* const* d_in, const int* in_sizes, int n_in,
                              void* d_out, int out_size) {
    const float4* x      = (const float4*)d_in[0];
    const float*  thresh = (const float*)d_in[1];
    float4*       out    = (float4*)d_out;

    // Elements per frame: total / T1; float4s per frame: /4.
    int S  = in_sizes[0] / IF_T1;
    int S4 = S / 4;

    IF_88957362634870_kernel<<<IF_BLOCKS, IF_THREADS>>>(x, thresh, out, S4);
}